// round 4
// baseline (speedup 1.0000x reference)
#include <cuda_runtime.h>
#include <math.h>

// ---------------- problem constants ----------------
#define NN    50000
#define FIN   256
#define FOUT  128
#define HH    128
#define DD    16
#define EE    (NN*DD)     // 800000
#define G4    512         // 4*H

// ---------------- scratch (device globals; no allocation allowed) ----------------
__device__ float    g_proj[(size_t)NN*FOUT];   // 25.6MB
__device__ float    g_ssrc[NN];
__device__ float    g_strg[NN];
__device__ float    g_scores[EE];
__device__ unsigned g_gmax;
__device__ int      g_seqsrc[EE];
__device__ float    g_seqatt[EE];
__device__ float    g_wcat[G4*256];            // permuted [x|h] weights, 512KB
__device__ float    g_bcat[G4];

// ---------------- helpers ----------------
__device__ __forceinline__ unsigned fenc(float f) {
    unsigned i = __float_as_uint(f);
    return (i & 0x80000000u) ? ~i : (i | 0x80000000u);
}
__device__ __forceinline__ float fdec(unsigned u) {
    return (u & 0x80000000u) ? __uint_as_float(u ^ 0x80000000u) : __uint_as_float(~u);
}
__device__ __forceinline__ float sigmoidf(float x) { return 1.0f / (1.0f + expf(-x)); }

// ---------------- kernel: build permuted concat weights ----------------
// chunk ch (0..3) covers hidden dims [ch*32, ch*32+32); within a chunk,
// col c: gate = c/32 (i,f,g,o), dim = ch*32 + c%32. K: 0..127 = w_ih, 128..255 = w_hh.
__global__ void prep_w_k(const float* __restrict__ wih, const float* __restrict__ whh,
                         const float* __restrict__ bih, const float* __restrict__ bhh) {
    int idx = blockIdx.x * blockDim.x + threadIdx.x;   // 0..131071
    int R = idx >> 8;
    int k = idx & 255;
    int ch = R >> 7, c = R & 127;
    int gate = c >> 5, dd = c & 31;
    int grow = gate * 128 + ch * 32 + dd;
    float v = (k < 128) ? wih[grow * 128 + k] : whh[grow * 128 + (k - 128)];
    g_wcat[R * 256 + k] = v;
    if (k == 0) g_bcat[R] = bih[grow] + bhh[grow];
}

// ---------------- kernel: proj + skip fused GEMM ----------------
// out cols 0..127 -> g_proj (X @ Wp^T), cols 128..255 -> d_out (X @ Wsk^T)
__global__ void gemm1_k(const float* __restrict__ x, const float* __restrict__ Wp,
                        const float* __restrict__ Wsk, float* __restrict__ out) {
    __shared__ float xs[64 * 33];
    __shared__ float ws[256 * 33];
    int tid = threadIdx.x;
    int tx = tid & 15, ty = tid >> 4;
    int n0 = blockIdx.x * 64;
    float acc[4][16];
#pragma unroll
    for (int i = 0; i < 4; i++)
#pragma unroll
        for (int j = 0; j < 16; j++) acc[i][j] = 0.0f;

    for (int k0 = 0; k0 < 256; k0 += 32) {
        __syncthreads();
#pragma unroll
        for (int v = 0; v < 8; v++) {
            int idx = tid + v * 256;
            int r = idx >> 5, kk = idx & 31;
            int n = n0 + r;
            xs[r * 33 + kk] = (n < NN) ? x[(size_t)n * 256 + k0 + kk] : 0.0f;
        }
#pragma unroll
        for (int v = 0; v < 32; v++) {
            int idx = tid + v * 256;
            int c = idx >> 5, kk = idx & 31;
            ws[c * 33 + kk] = (c < 128) ? Wp[c * 256 + k0 + kk]
                                        : Wsk[(c - 128) * 256 + k0 + kk];
        }
        __syncthreads();
#pragma unroll
        for (int kk = 0; kk < 32; kk++) {
            float uv[4];
#pragma unroll
            for (int i = 0; i < 4; i++) uv[i] = xs[(ty * 4 + i) * 33 + kk];
#pragma unroll
            for (int j = 0; j < 16; j++) {
                float wv = ws[(tx + 16 * j) * 33 + kk];
#pragma unroll
                for (int i = 0; i < 4; i++) acc[i][j] = fmaf(uv[i], wv, acc[i][j]);
            }
        }
    }
#pragma unroll
    for (int i = 0; i < 4; i++) {
        int n = n0 + ty * 4 + i;
        if (n >= NN) continue;
#pragma unroll
        for (int j = 0; j < 16; j++) {
            int c = tx + 16 * j;
            if (c < 128) g_proj[(size_t)n * 128 + c] = acc[i][j];
            else         out[(size_t)n * 128 + (c - 128)] = acc[i][j];
        }
    }
}

// ---------------- kernel: per-node attention dots ----------------
__global__ void sdots_k(const float* __restrict__ as, const float* __restrict__ at) {
    int gtid = blockIdx.x * blockDim.x + threadIdx.x;
    int warp = gtid >> 5;
    int lane = gtid & 31;
    if (warp >= NN) return;
    const float* p = g_proj + (size_t)warp * 128;
    float s1 = 0.0f, s2 = 0.0f;
#pragma unroll
    for (int d = lane; d < 128; d += 32) {
        float v = p[d];
        s1 = fmaf(v, as[d], s1);
        s2 = fmaf(v, at[d], s2);
    }
#pragma unroll
    for (int o = 16; o; o >>= 1) {
        s1 += __shfl_xor_sync(0xffffffffu, s1, o);
        s2 += __shfl_xor_sync(0xffffffffu, s2, o);
    }
    if (lane == 0) { g_ssrc[warp] = s1; g_strg[warp] = s2; }
}

__global__ void initmax_k() { g_gmax = 0u; }

// ---------------- kernel: edge scores + global max ----------------
__global__ void scores_k(const int* __restrict__ ei) {
    int e = blockIdx.x * blockDim.x + threadIdx.x;   // EE = 3125*256 exact
    int s = ei[e];
    int t = ei[EE + e];
    float sc = g_ssrc[s] + g_strg[t];
    sc = (sc >= 0.0f) ? sc : 0.2f * sc;
    g_scores[e] = sc;
    float m = sc;
#pragma unroll
    for (int o = 16; o; o >>= 1) m = fmaxf(m, __shfl_xor_sync(0xffffffffu, m, o));
    __shared__ float wm[8];
    int lane = threadIdx.x & 31, wid = threadIdx.x >> 5;
    if (lane == 0) wm[wid] = m;
    __syncthreads();
    if (threadIdx.x == 0) {
        float mm = wm[0];
#pragma unroll
        for (int w = 1; w < 8; w++) mm = fmaxf(mm, wm[w]);
        atomicMax(&g_gmax, fenc(mm));
    }
}

// ---------------- kernel: softmax + stable sort (desc att, tie -> desc idx) ----------------
__global__ void sort_k(const int* __restrict__ ei) {
    int n = blockIdx.x * blockDim.x + threadIdx.x;
    if (n >= NN) return;
    float gmax = fdec(g_gmax);
    float ev[DD], srt[DD];
    int idx[DD];
    float denom = 0.0f;
#pragma unroll
    for (int j = 0; j < DD; j++) {
        float e = expf(g_scores[n * DD + j] - gmax);
        ev[j] = e;
        denom += e;
    }
    denom += 1e-16f;
    // insertion sort, descending; "<=" shift => later (larger) original index first on ties,
    // matching stable-ascending argsort followed by reversal.
    for (int j = 0; j < DD; j++) {
        float key = ev[j];
        int pos = j;
        while (pos > 0 && srt[pos - 1] <= key) {
            srt[pos] = srt[pos - 1];
            idx[pos] = idx[pos - 1];
            pos--;
        }
        srt[pos] = key;
        idx[pos] = j;
    }
    float inv = 1.0f / denom;
#pragma unroll
    for (int t = 0; t < DD; t++) {
        int j = idx[t];
        g_seqsrc[n * DD + t] = ei[n * DD + j];     // src of edge
        g_seqatt[n * DD + t] = srt[t] * inv;
    }
}

// ---------------- kernel: backward-direction LSTM + epilogue ----------------
// 64 nodes per block. u = [x_t | h] in SMEM (stride 257). Per timestep, 4 chunks;
// each chunk computes 128 gate cols = (i,f,g,o) x 32 hidden dims, then updates c,h.
#define LSTM_SMEM_FLOATS (64*257 + 3*64*129 + 128*33)

__global__ __launch_bounds__(256, 1) void lstm_k(const float* __restrict__ bias,
                                                 float* __restrict__ out) {
    extern __shared__ float sm[];
    float* u   = sm;                 // [64][257]  cols 0..127 x_t, 128..255 h
    float* csm = u + 64 * 257;       // [64][129]
    float* gb  = csm + 64 * 129;     // [64][129]  gate staging for current chunk
    float* hn  = gb + 64 * 129;      // [64][129]  new h
    float* wsm = hn + 64 * 129;      // [128][33]  weight tile

    int tid = threadIdx.x;
    int tx = tid & 15, ty = tid >> 4;
    int n0 = blockIdx.x * 64;

    // init: x_0 gather, h=0, c=0
    for (int idx = tid; idx < 64 * 128; idx += 256) {
        int r = idx >> 7, d = idx & 127;
        int n = n0 + r;
        float xv = 0.0f;
        if (n < NN) {
            int s = g_seqsrc[n * DD + 0];
            float a = g_seqatt[n * DD + 0];
            xv = g_proj[(size_t)s * 128 + d] * a;
        }
        u[r * 257 + d] = xv;
        u[r * 257 + 128 + d] = 0.0f;
        csm[r * 129 + d] = 0.0f;
    }
    __syncthreads();

    for (int t = 0; t < DD; t++) {
#pragma unroll 1
        for (int ch = 0; ch < 4; ch++) {
            float acc[4][8];
#pragma unroll
            for (int i = 0; i < 4; i++)
#pragma unroll
                for (int j = 0; j < 8; j++) acc[i][j] = 0.0f;

#pragma unroll 1
            for (int k0 = 0; k0 < 256; k0 += 32) {
                __syncthreads();
#pragma unroll
                for (int v = 0; v < 16; v++) {
                    int idx = tid + v * 256;
                    int c = idx >> 5, kk = idx & 31;
                    wsm[c * 33 + kk] = g_wcat[(ch * 128 + c) * 256 + k0 + kk];
                }
                __syncthreads();
#pragma unroll
                for (int kk = 0; kk < 32; kk++) {
                    float uv[4];
#pragma unroll
                    for (int i = 0; i < 4; i++) uv[i] = u[(ty * 4 + i) * 257 + k0 + kk];
#pragma unroll
                    for (int j = 0; j < 8; j++) {
                        float wv = wsm[(tx + 16 * j) * 33 + kk];
#pragma unroll
                        for (int i = 0; i < 4; i++) acc[i][j] = fmaf(uv[i], wv, acc[i][j]);
                    }
                }
            }
            __syncthreads();
#pragma unroll
            for (int i = 0; i < 4; i++)
#pragma unroll
                for (int j = 0; j < 8; j++) {
                    int c = tx + 16 * j;
                    gb[(ty * 4 + i) * 129 + c] = acc[i][j] + g_bcat[ch * 128 + c];
                }
            __syncthreads();
            // c/h update for hidden dims ch*32 .. ch*32+31
            for (int idx = tid; idx < 64 * 32; idx += 256) {
                int r = idx >> 5, dd2 = idx & 31;
                int d = ch * 32 + dd2;
                float ig = sigmoidf(gb[r * 129 + dd2]);
                float fg = sigmoidf(gb[r * 129 + 32 + dd2]);
                float gg = tanhf(gb[r * 129 + 64 + dd2]);
                float og = sigmoidf(gb[r * 129 + 96 + dd2]);
                float c_ = fg * csm[r * 129 + d] + ig * gg;
                csm[r * 129 + d] = c_;
                hn[r * 129 + d] = og * tanhf(c_);
            }
            __syncthreads();
        }
        if (t < DD - 1) {
            for (int idx = tid; idx < 64 * 128; idx += 256) {
                int r = idx >> 7, d = idx & 127;
                int n = n0 + r;
                u[r * 257 + 128 + d] = hn[r * 129 + d];
                float xv = 0.0f;
                if (n < NN) {
                    int s = g_seqsrc[n * DD + t + 1];
                    float a = g_seqatt[n * DD + t + 1];
                    xv = g_proj[(size_t)s * 128 + d] * a;
                }
                u[r * 257 + d] = xv;
            }
            __syncthreads();
        } else {
            for (int idx = tid; idx < 64 * 128; idx += 256) {
                int r = idx >> 7, d = idx & 127;
                int n = n0 + r;
                if (n < NN) {
                    float v = hn[r * 129 + d] + out[(size_t)n * 128 + d] + bias[d];
                    out[(size_t)n * 128 + d] = (v >= 0.0f) ? v : 0.01f * v;
                }
            }
        }
    }
}

// ---------------- launch ----------------
extern "C" void kernel_launch(void* const* d_in, const int* in_sizes, int n_in,
                              void* d_out, int out_size) {
    const float* x    = (const float*)d_in[0];
    const float* Wp   = (const float*)d_in[1];
    const float* asrc = (const float*)d_in[2];
    const float* atrg = (const float*)d_in[3];
    const float* Wsk  = (const float*)d_in[4];
    const float* bias = (const float*)d_in[5];
    // d_in[6..9]: forward-direction weights, unused by the reference
    const float* wihb = (const float*)d_in[10];
    const float* whhb = (const float*)d_in[11];
    const float* bihb = (const float*)d_in[12];
    const float* bhhb = (const float*)d_in[13];
    const int*   ei   = (const int*)d_in[14];
    float* out = (float*)d_out;

    (void)in_sizes; (void)n_in; (void)out_size;

    cudaFuncSetAttribute(lstm_k, cudaFuncAttributeMaxDynamicSharedMemorySize,
                         LSTM_SMEM_FLOATS * (int)sizeof(float));

    prep_w_k<<<512, 256>>>(wihb, whhb, bihb, bhhb);
    gemm1_k<<<(NN + 63) / 64, 256>>>(x, Wp, Wsk, out);
    sdots_k<<<(NN * 32 + 255) / 256, 256>>>(asrc, atrg);
    initmax_k<<<1, 1>>>();
    scores_k<<<EE / 256, 256>>>(ei);
    sort_k<<<(NN + 255) / 256, 256>>>(ei);
    lstm_k<<<(NN + 63) / 64, 256, LSTM_SMEM_FLOATS * (int)sizeof(float)>>>(bias, out);
}

// round 5
// speedup vs baseline: 1.5448x; 1.5448x over previous
#include <cuda_runtime.h>
#include <math.h>

// ---------------- problem constants ----------------
#define NN    50000
#define FIN   256
#define FOUT  128
#define HH    128
#define DD    16
#define EE    (NN*DD)     // 800000
#define G4    512         // 4*H

// ---------------- scratch (device globals; no allocation allowed) ----------------
__device__ float    g_proj[(size_t)NN*FOUT];   // 25.6MB
__device__ float    g_P2[(size_t)NN*G4];       // 102.4MB  P2 = proj @ w_ih^T (permuted cols)
__device__ float    g_ssrc[NN];
__device__ float    g_strg[NN];
__device__ float    g_scores[EE];
__device__ unsigned g_gmax;
__device__ int      g_seqsrc[EE];
__device__ float    g_seqatt[EE];
__device__ float    g_wih_p[G4*HH];            // permuted w_ih  [512][128]
__device__ float    g_whh_p[G4*HH];            // permuted w_hh  [512][128]
__device__ float    g_bcat[G4];

// ---------------- helpers ----------------
__device__ __forceinline__ unsigned fenc(float f) {
    unsigned i = __float_as_uint(f);
    return (i & 0x80000000u) ? ~i : (i | 0x80000000u);
}
__device__ __forceinline__ float fdec(unsigned u) {
    return (u & 0x80000000u) ? __uint_as_float(u ^ 0x80000000u) : __uint_as_float(~u);
}
__device__ __forceinline__ float sigmoidf_(float x) { return 1.0f / (1.0f + expf(-x)); }

// ---------------- kernel: build permuted weights ----------------
// Permutation: R = ch*128 + c, with gate = c/32 (i,f,g,o), dim = ch*32 + c%32.
// Row in original layout: grow = gate*128 + ch*32 + dim%32.
__global__ void prep_w_k(const float* __restrict__ wih, const float* __restrict__ whh,
                         const float* __restrict__ bih, const float* __restrict__ bhh) {
    int idx = blockIdx.x * blockDim.x + threadIdx.x;   // 0..65535
    int R = idx >> 7;
    int k = idx & 127;
    int ch = R >> 7, c = R & 127;
    int gate = c >> 5, dd = c & 31;
    int grow = gate * 128 + ch * 32 + dd;
    g_wih_p[R * 128 + k] = wih[grow * 128 + k];
    g_whh_p[R * 128 + k] = whh[grow * 128 + k];
    if (k == 0) g_bcat[R] = bih[grow] + bhh[grow];
}

// ---------------- kernel: proj + skip fused GEMM ----------------
// out cols 0..127 -> g_proj (X @ Wp^T), cols 128..255 -> d_out (X @ Wsk^T)
__global__ void gemm1_k(const float* __restrict__ x, const float* __restrict__ Wp,
                        const float* __restrict__ Wsk, float* __restrict__ out) {
    __shared__ float xs[64 * 33];
    __shared__ float ws[256 * 33];
    int tid = threadIdx.x;
    int tx = tid & 15, ty = tid >> 4;
    int n0 = blockIdx.x * 64;
    float acc[4][16];
#pragma unroll
    for (int i = 0; i < 4; i++)
#pragma unroll
        for (int j = 0; j < 16; j++) acc[i][j] = 0.0f;

    for (int k0 = 0; k0 < 256; k0 += 32) {
        __syncthreads();
#pragma unroll
        for (int v = 0; v < 8; v++) {
            int idx = tid + v * 256;
            int r = idx >> 5, kk = idx & 31;
            int n = n0 + r;
            xs[r * 33 + kk] = (n < NN) ? x[(size_t)n * 256 + k0 + kk] : 0.0f;
        }
#pragma unroll
        for (int v = 0; v < 32; v++) {
            int idx = tid + v * 256;
            int c = idx >> 5, kk = idx & 31;
            ws[c * 33 + kk] = (c < 128) ? Wp[c * 256 + k0 + kk]
                                        : Wsk[(c - 128) * 256 + k0 + kk];
        }
        __syncthreads();
#pragma unroll
        for (int kk = 0; kk < 32; kk++) {
            float uv[4];
#pragma unroll
            for (int i = 0; i < 4; i++) uv[i] = xs[(ty * 4 + i) * 33 + kk];
#pragma unroll
            for (int j = 0; j < 16; j++) {
                float wv = ws[(tx + 16 * j) * 33 + kk];
#pragma unroll
                for (int i = 0; i < 4; i++) acc[i][j] = fmaf(uv[i], wv, acc[i][j]);
            }
        }
    }
#pragma unroll
    for (int i = 0; i < 4; i++) {
        int n = n0 + ty * 4 + i;
        if (n >= NN) continue;
#pragma unroll
        for (int j = 0; j < 16; j++) {
            int c = tx + 16 * j;
            if (c < 128) g_proj[(size_t)n * 128 + c] = acc[i][j];
            else         out[(size_t)n * 128 + (c - 128)] = acc[i][j];
        }
    }
}

// ---------------- kernel: P2 = proj @ w_ih_p^T  (K=128, N=512 in 2 col-halves) ----
__global__ void p2_k() {
    __shared__ float xs[64 * 33];
    __shared__ float ws[256 * 33];
    int tid = threadIdx.x;
    int tx = tid & 15, ty = tid >> 4;
    int n0 = blockIdx.x * 64;
    int coff = blockIdx.y * 256;
    float acc[4][16];
#pragma unroll
    for (int i = 0; i < 4; i++)
#pragma unroll
        for (int j = 0; j < 16; j++) acc[i][j] = 0.0f;

    for (int k0 = 0; k0 < 128; k0 += 32) {
        __syncthreads();
#pragma unroll
        for (int v = 0; v < 8; v++) {
            int idx = tid + v * 256;
            int r = idx >> 5, kk = idx & 31;
            int n = n0 + r;
            xs[r * 33 + kk] = (n < NN) ? g_proj[(size_t)n * 128 + k0 + kk] : 0.0f;
        }
#pragma unroll
        for (int v = 0; v < 32; v++) {
            int idx = tid + v * 256;
            int c = idx >> 5, kk = idx & 31;
            ws[c * 33 + kk] = g_wih_p[(coff + c) * 128 + k0 + kk];
        }
        __syncthreads();
#pragma unroll
        for (int kk = 0; kk < 32; kk++) {
            float uv[4];
#pragma unroll
            for (int i = 0; i < 4; i++) uv[i] = xs[(ty * 4 + i) * 33 + kk];
#pragma unroll
            for (int j = 0; j < 16; j++) {
                float wv = ws[(tx + 16 * j) * 33 + kk];
#pragma unroll
                for (int i = 0; i < 4; i++) acc[i][j] = fmaf(uv[i], wv, acc[i][j]);
            }
        }
    }
#pragma unroll
    for (int i = 0; i < 4; i++) {
        int n = n0 + ty * 4 + i;
        if (n >= NN) continue;
#pragma unroll
        for (int j = 0; j < 16; j++)
            g_P2[(size_t)n * 512 + coff + tx + 16 * j] = acc[i][j];
    }
}

// ---------------- kernel: per-node attention dots ----------------
__global__ void sdots_k(const float* __restrict__ as, const float* __restrict__ at) {
    int gtid = blockIdx.x * blockDim.x + threadIdx.x;
    int warp = gtid >> 5;
    int lane = gtid & 31;
    if (warp >= NN) return;
    const float* p = g_proj + (size_t)warp * 128;
    float s1 = 0.0f, s2 = 0.0f;
#pragma unroll
    for (int d = lane; d < 128; d += 32) {
        float v = p[d];
        s1 = fmaf(v, as[d], s1);
        s2 = fmaf(v, at[d], s2);
    }
#pragma unroll
    for (int o = 16; o; o >>= 1) {
        s1 += __shfl_xor_sync(0xffffffffu, s1, o);
        s2 += __shfl_xor_sync(0xffffffffu, s2, o);
    }
    if (lane == 0) { g_ssrc[warp] = s1; g_strg[warp] = s2; }
}

__global__ void initmax_k() { g_gmax = 0u; }

// ---------------- kernel: edge scores + global max ----------------
__global__ void scores_k(const int* __restrict__ ei) {
    int e = blockIdx.x * blockDim.x + threadIdx.x;   // EE = 3125*256 exact
    int s = ei[e];
    int t = ei[EE + e];
    float sc = g_ssrc[s] + g_strg[t];
    sc = (sc >= 0.0f) ? sc : 0.2f * sc;
    g_scores[e] = sc;
    float m = sc;
#pragma unroll
    for (int o = 16; o; o >>= 1) m = fmaxf(m, __shfl_xor_sync(0xffffffffu, m, o));
    __shared__ float wm[8];
    int lane = threadIdx.x & 31, wid = threadIdx.x >> 5;
    if (lane == 0) wm[wid] = m;
    __syncthreads();
    if (threadIdx.x == 0) {
        float mm = wm[0];
#pragma unroll
        for (int w = 1; w < 8; w++) mm = fmaxf(mm, wm[w]);
        atomicMax(&g_gmax, fenc(mm));
    }
}

// ---------------- kernel: softmax + stable sort (desc att, tie -> desc idx) ----------------
__global__ void sort_k(const int* __restrict__ ei) {
    int n = blockIdx.x * blockDim.x + threadIdx.x;
    if (n >= NN) return;
    float gmax = fdec(g_gmax);
    float ev[DD], srt[DD];
    int idx[DD];
    float denom = 0.0f;
#pragma unroll
    for (int j = 0; j < DD; j++) {
        float e = expf(g_scores[n * DD + j] - gmax);
        ev[j] = e;
        denom += e;
    }
    denom += 1e-16f;
    for (int j = 0; j < DD; j++) {
        float key = ev[j];
        int pos = j;
        while (pos > 0 && srt[pos - 1] <= key) {
            srt[pos] = srt[pos - 1];
            idx[pos] = idx[pos - 1];
            pos--;
        }
        srt[pos] = key;
        idx[pos] = j;
    }
    float inv = 1.0f / denom;
#pragma unroll
    for (int t = 0; t < DD; t++) {
        int j = idx[t];
        g_seqsrc[n * DD + t] = ei[n * DD + j];     // src of edge
        g_seqatt[n * DD + t] = srt[t] * inv;
    }
}

// ---------------- kernel: backward-direction LSTM (K=128 recurrence) + epilogue ----
// gates[n,t] = att[n,t] * P2[src[n,t]] + bias + h @ w_hh_p^T
// 64 nodes / block, 256 threads. h, c, gate-staging, new-h in SMEM; w_hh streamed.
#define LSTM_SM_FLOATS (4*64*129 + 128*33 + 128)

__global__ __launch_bounds__(256, 1) void lstm_k(const float* __restrict__ bias,
                                                 float* __restrict__ out) {
    extern __shared__ float sm[];
    float* u    = sm;                    // [64][129]  h
    float* csm  = u   + 64 * 129;        // [64][129]  c
    float* gb   = csm + 64 * 129;        // [64][129]  gate staging (current chunk)
    float* hn   = gb  + 64 * 129;        // [64][129]  new h
    float* wsm  = hn  + 64 * 129;        // [128][33]  w_hh tile
    float* satt = wsm + 128 * 33;        // [64]
    int*   ssrc = (int*)(satt + 64);     // [64]

    int tid = threadIdx.x;
    int tx = tid & 15, ty = tid >> 4;
    int n0 = blockIdx.x * 64;

    // init h=0, c=0
    for (int idx = tid; idx < 64 * 128; idx += 256) {
        int r = idx >> 7, d = idx & 127;
        u[r * 129 + d] = 0.0f;
        csm[r * 129 + d] = 0.0f;
    }
    __syncthreads();

    for (int t = 0; t < DD; t++) {
        if (tid < 64) {
            int n = n0 + tid;
            if (n < NN) {
                ssrc[tid] = g_seqsrc[n * DD + t];
                satt[tid] = g_seqatt[n * DD + t];
            } else {
                ssrc[tid] = 0;
                satt[tid] = 0.0f;
            }
        }
        __syncthreads();

#pragma unroll 1
        for (int ch = 0; ch < 4; ch++) {
            // acc init: bias + att * P2[src] (gather from L2/HBM)
            float acc[4][8];
#pragma unroll
            for (int i = 0; i < 4; i++) {
                int r = ty * 4 + i;
                int s = ssrc[r];
                float a = satt[r];
                const float* p2 = g_P2 + (size_t)s * 512 + ch * 128;
#pragma unroll
                for (int j = 0; j < 8; j++) {
                    int c = tx + 16 * j;
                    acc[i][j] = fmaf(a, p2[c], g_bcat[ch * 128 + c]);
                }
            }

            // h @ w_hh_p^T, K = 128 in 4 tiles of 32
#pragma unroll 1
            for (int k0 = 0; k0 < 128; k0 += 32) {
                __syncthreads();
#pragma unroll
                for (int v = 0; v < 16; v++) {
                    int idx = tid + v * 256;
                    int c = idx >> 5, kk = idx & 31;
                    wsm[c * 33 + kk] = g_whh_p[(ch * 128 + c) * 128 + k0 + kk];
                }
                __syncthreads();
#pragma unroll
                for (int kk = 0; kk < 32; kk++) {
                    float uv[4];
#pragma unroll
                    for (int i = 0; i < 4; i++) uv[i] = u[(ty * 4 + i) * 129 + k0 + kk];
#pragma unroll
                    for (int j = 0; j < 8; j++) {
                        float wv = wsm[(tx + 16 * j) * 33 + kk];
#pragma unroll
                        for (int i = 0; i < 4; i++) acc[i][j] = fmaf(uv[i], wv, acc[i][j]);
                    }
                }
            }
            __syncthreads();
#pragma unroll
            for (int i = 0; i < 4; i++)
#pragma unroll
                for (int j = 0; j < 8; j++)
                    gb[(ty * 4 + i) * 129 + tx + 16 * j] = acc[i][j];
            __syncthreads();
            // c/h update for hidden dims ch*32 .. ch*32+31
            for (int idx = tid; idx < 64 * 32; idx += 256) {
                int r = idx >> 5, dd2 = idx & 31;
                int d = ch * 32 + dd2;
                float ig = sigmoidf_(gb[r * 129 + dd2]);
                float fg = sigmoidf_(gb[r * 129 + 32 + dd2]);
                float gg = tanhf(gb[r * 129 + 64 + dd2]);
                float og = sigmoidf_(gb[r * 129 + 96 + dd2]);
                float c_ = fg * csm[r * 129 + d] + ig * gg;
                csm[r * 129 + d] = c_;
                hn[r * 129 + d] = og * tanhf(c_);
            }
            __syncthreads();
        }

        if (t < DD - 1) {
            for (int idx = tid; idx < 64 * 128; idx += 256) {
                int r = idx >> 7, d = idx & 127;
                u[r * 129 + d] = hn[r * 129 + d];
            }
            __syncthreads();
        } else {
            for (int idx = tid; idx < 64 * 128; idx += 256) {
                int r = idx >> 7, d = idx & 127;
                int n = n0 + r;
                if (n < NN) {
                    float v = hn[r * 129 + d] + out[(size_t)n * 128 + d] + bias[d];
                    out[(size_t)n * 128 + d] = (v >= 0.0f) ? v : 0.01f * v;
                }
            }
        }
    }
}

// ---------------- launch ----------------
extern "C" void kernel_launch(void* const* d_in, const int* in_sizes, int n_in,
                              void* d_out, int out_size) {
    const float* x    = (const float*)d_in[0];
    const float* Wp   = (const float*)d_in[1];
    const float* asrc = (const float*)d_in[2];
    const float* atrg = (const float*)d_in[3];
    const float* Wsk  = (const float*)d_in[4];
    const float* bias = (const float*)d_in[5];
    // d_in[6..9]: forward-direction weights, unused by the reference
    const float* wihb = (const float*)d_in[10];
    const float* whhb = (const float*)d_in[11];
    const float* bihb = (const float*)d_in[12];
    const float* bhhb = (const float*)d_in[13];
    const int*   ei   = (const int*)d_in[14];
    float* out = (float*)d_out;

    (void)in_sizes; (void)n_in; (void)out_size;

    cudaFuncSetAttribute(lstm_k, cudaFuncAttributeMaxDynamicSharedMemorySize,
                         LSTM_SM_FLOATS * (int)sizeof(float));

    prep_w_k<<<256, 256>>>(wihb, whhb, bihb, bhhb);
    gemm1_k<<<(NN + 63) / 64, 256>>>(x, Wp, Wsk, out);
    {
        dim3 g((NN + 63) / 64, 2);
        p2_k<<<g, 256>>>();
    }
    sdots_k<<<(NN * 32 + 255) / 256, 256>>>(asrc, atrg);
    initmax_k<<<1, 1>>>();
    scores_k<<<EE / 256, 256>>>(ei);
    sort_k<<<(NN + 255) / 256, 256>>>(ei);
    lstm_k<<<(NN + 63) / 64, 256, LSTM_SM_FLOATS * (int)sizeof(float)>>>(bias, out);
}

// round 6
// speedup vs baseline: 2.1060x; 1.3633x over previous
#include <cuda_runtime.h>
#include <math.h>

// ---------------- problem constants ----------------
#define NN    50000
#define FIN   256
#define FOUT  128
#define HH    128
#define DD    16
#define EE    (NN*DD)     // 800000
#define G4    512         // 4*H

// ---------------- scratch ----------------
__device__ float    g_proj[(size_t)NN*FOUT];   // 25.6MB
__device__ float    g_P2[(size_t)NN*G4];       // 102.4MB  P2 = proj @ w_ih^T (permuted cols)
__device__ float    g_ssrc[NN];
__device__ float    g_strg[NN];
__device__ float    g_scores[EE];
__device__ unsigned g_gmax;
__device__ int      g_seqsrc[EE];
__device__ float    g_seqatt[EE];
__device__ float    g_wih_p[G4*HH];            // permuted w_ih  [512 rows][128 k]  (row-major)
__device__ float    g_whh_pT[HH*G4];           // permuted w_hh  [128 k][512 cols]  (K-MAJOR)
__device__ float    g_bcat[G4];

// ---------------- helpers ----------------
__device__ __forceinline__ unsigned fenc(float f) {
    unsigned i = __float_as_uint(f);
    return (i & 0x80000000u) ? ~i : (i | 0x80000000u);
}
__device__ __forceinline__ float fdec(unsigned u) {
    return (u & 0x80000000u) ? __uint_as_float(u ^ 0x80000000u) : __uint_as_float(~u);
}
__device__ __forceinline__ float tanh_fast(float x) {
    float r;
    asm("tanh.approx.f32 %0, %1;" : "=f"(r) : "f"(x));
    return r;
}
__device__ __forceinline__ float sig_fast(float x) {
    return fmaf(tanh_fast(0.5f * x), 0.5f, 0.5f);
}

// ---------------- kernel: build permuted weights ----------------
// Permutation: R = ch*128 + c, c = gate*32 + dd -> original row grow = gate*128 + ch*32 + dd.
__global__ void prep_w_k(const float* __restrict__ wih, const float* __restrict__ whh,
                         const float* __restrict__ bih, const float* __restrict__ bhh) {
    int idx = blockIdx.x * blockDim.x + threadIdx.x;   // 0..65535
    int R = idx >> 7;
    int k = idx & 127;
    int ch = R >> 7, c = R & 127;
    int gate = c >> 5, dd = c & 31;
    int grow = gate * 128 + ch * 32 + dd;
    g_wih_p[R * 128 + k]  = wih[grow * 128 + k];
    g_whh_pT[k * 512 + R] = whh[grow * 128 + k];
    if (k == 0) g_bcat[R] = bih[grow] + bhh[grow];
}

// ---------------- kernel: proj + skip fused GEMM (8x8 tiles) ----------------
// 64 rows x 256 cols per block; cols 0..127 -> g_proj, 128..255 -> d_out.
__global__ __launch_bounds__(256) void gemm1_k(const float* __restrict__ x,
                                               const float* __restrict__ Wp,
                                               const float* __restrict__ Wsk,
                                               float* __restrict__ out) {
    __shared__ float xs[64 * 33];
    __shared__ float ws[256 * 33];
    int tid = threadIdx.x, lane = tid & 31, wrp = tid >> 5;
    int n0 = blockIdx.x * 64;
    float acc[8][8];
#pragma unroll
    for (int i = 0; i < 8; i++)
#pragma unroll
        for (int j = 0; j < 8; j++) acc[i][j] = 0.0f;

    for (int k0 = 0; k0 < 256; k0 += 32) {
        __syncthreads();
#pragma unroll
        for (int v = 0; v < 8; v++) {
            int idx = tid + v * 256;
            int r = idx >> 5, kk = idx & 31;
            int n = n0 + r;
            xs[r * 33 + kk] = (n < NN) ? x[(size_t)n * 256 + k0 + kk] : 0.0f;
        }
#pragma unroll
        for (int v = 0; v < 32; v++) {
            int idx = tid + v * 256;
            int c = idx >> 5, kk = idx & 31;
            ws[c * 33 + kk] = (c < 128) ? Wp[c * 256 + k0 + kk]
                                        : Wsk[(c - 128) * 256 + k0 + kk];
        }
        __syncthreads();
#pragma unroll 4
        for (int kk = 0; kk < 32; kk++) {
            float uv[8], wv[8];
#pragma unroll
            for (int i = 0; i < 8; i++) uv[i] = xs[(wrp * 8 + i) * 33 + kk];
#pragma unroll
            for (int j = 0; j < 8; j++) wv[j] = ws[(j * 32 + lane) * 33 + kk];
#pragma unroll
            for (int i = 0; i < 8; i++)
#pragma unroll
                for (int j = 0; j < 8; j++) acc[i][j] = fmaf(uv[i], wv[j], acc[i][j]);
        }
    }
#pragma unroll
    for (int i = 0; i < 8; i++) {
        int n = n0 + wrp * 8 + i;
        if (n >= NN) continue;
#pragma unroll
        for (int j = 0; j < 8; j++) {
            int c = j * 32 + lane;
            if (c < 128) g_proj[(size_t)n * 128 + c] = acc[i][j];
            else         out[(size_t)n * 128 + (c - 128)] = acc[i][j];
        }
    }
}

// ---------------- kernel: P2 = proj @ w_ih_p^T (8x8 tiles, 2 col-halves) ----------
__global__ __launch_bounds__(256) void p2_k() {
    __shared__ float xs[64 * 33];
    __shared__ float ws[256 * 33];
    int tid = threadIdx.x, lane = tid & 31, wrp = tid >> 5;
    int n0 = blockIdx.x * 64;
    int coff = blockIdx.y * 256;
    float acc[8][8];
#pragma unroll
    for (int i = 0; i < 8; i++)
#pragma unroll
        for (int j = 0; j < 8; j++) acc[i][j] = 0.0f;

    for (int k0 = 0; k0 < 128; k0 += 32) {
        __syncthreads();
#pragma unroll
        for (int v = 0; v < 8; v++) {
            int idx = tid + v * 256;
            int r = idx >> 5, kk = idx & 31;
            int n = n0 + r;
            xs[r * 33 + kk] = (n < NN) ? g_proj[(size_t)n * 128 + k0 + kk] : 0.0f;
        }
#pragma unroll
        for (int v = 0; v < 32; v++) {
            int idx = tid + v * 256;
            int c = idx >> 5, kk = idx & 31;
            ws[c * 33 + kk] = g_wih_p[(coff + c) * 128 + k0 + kk];
        }
        __syncthreads();
#pragma unroll 4
        for (int kk = 0; kk < 32; kk++) {
            float uv[8], wv[8];
#pragma unroll
            for (int i = 0; i < 8; i++) uv[i] = xs[(wrp * 8 + i) * 33 + kk];
#pragma unroll
            for (int j = 0; j < 8; j++) wv[j] = ws[(j * 32 + lane) * 33 + kk];
#pragma unroll
            for (int i = 0; i < 8; i++)
#pragma unroll
                for (int j = 0; j < 8; j++) acc[i][j] = fmaf(uv[i], wv[j], acc[i][j]);
        }
    }
#pragma unroll
    for (int i = 0; i < 8; i++) {
        int n = n0 + wrp * 8 + i;
        if (n >= NN) continue;
#pragma unroll
        for (int j = 0; j < 8; j++)
            g_P2[(size_t)n * 512 + coff + j * 32 + lane] = acc[i][j];
    }
}

// ---------------- kernel: per-node attention dots ----------------
__global__ void sdots_k(const float* __restrict__ as, const float* __restrict__ at) {
    int gtid = blockIdx.x * blockDim.x + threadIdx.x;
    int warp = gtid >> 5;
    int lane = gtid & 31;
    if (warp >= NN) return;
    const float* p = g_proj + (size_t)warp * 128;
    float s1 = 0.0f, s2 = 0.0f;
#pragma unroll
    for (int d = lane; d < 128; d += 32) {
        float v = p[d];
        s1 = fmaf(v, as[d], s1);
        s2 = fmaf(v, at[d], s2);
    }
#pragma unroll
    for (int o = 16; o; o >>= 1) {
        s1 += __shfl_xor_sync(0xffffffffu, s1, o);
        s2 += __shfl_xor_sync(0xffffffffu, s2, o);
    }
    if (lane == 0) { g_ssrc[warp] = s1; g_strg[warp] = s2; }
}

__global__ void initmax_k() { g_gmax = 0u; }

// ---------------- kernel: edge scores + global max ----------------
__global__ void scores_k(const int* __restrict__ ei) {
    int e = blockIdx.x * blockDim.x + threadIdx.x;
    int s = ei[e];
    int t = ei[EE + e];
    float sc = g_ssrc[s] + g_strg[t];
    sc = (sc >= 0.0f) ? sc : 0.2f * sc;
    g_scores[e] = sc;
    float m = sc;
#pragma unroll
    for (int o = 16; o; o >>= 1) m = fmaxf(m, __shfl_xor_sync(0xffffffffu, m, o));
    __shared__ float wm[8];
    int lane = threadIdx.x & 31, wid = threadIdx.x >> 5;
    if (lane == 0) wm[wid] = m;
    __syncthreads();
    if (threadIdx.x == 0) {
        float mm = wm[0];
#pragma unroll
        for (int w = 1; w < 8; w++) mm = fmaxf(mm, wm[w]);
        atomicMax(&g_gmax, fenc(mm));
    }
}

// ---------------- kernel: softmax + stable sort ----------------
__global__ void sort_k(const int* __restrict__ ei) {
    int n = blockIdx.x * blockDim.x + threadIdx.x;
    if (n >= NN) return;
    float gmax = fdec(g_gmax);
    float ev[DD], srt[DD];
    int idx[DD];
    float denom = 0.0f;
#pragma unroll
    for (int j = 0; j < DD; j++) {
        float e = expf(g_scores[n * DD + j] - gmax);
        ev[j] = e;
        denom += e;
    }
    denom += 1e-16f;
    for (int j = 0; j < DD; j++) {
        float key = ev[j];
        int pos = j;
        while (pos > 0 && srt[pos - 1] <= key) {
            srt[pos] = srt[pos - 1];
            idx[pos] = idx[pos - 1];
            pos--;
        }
        srt[pos] = key;
        idx[pos] = j;
    }
    float inv = 1.0f / denom;
#pragma unroll
    for (int t = 0; t < DD; t++) {
        int j = idx[t];
        g_seqsrc[n * DD + t] = ei[n * DD + j];
        g_seqatt[n * DD + t] = srt[t] * inv;
    }
}

// ---------------- kernel: backward LSTM, 8x8 tiles, c in registers ----------------
// 64 nodes / block, 256 threads (8 warps). warp owns 8 rows; lane owns dims
// {0,32,64,96}+lane across two passes (pass covers 2 chunks = 256 gate cols).
// gates[n] = att*P2[src] + bias + h @ w_hh^T ; c kept in registers.
#define U_STR 132
#define W_STR 260
#define LSTM_SM_FLOATS (2*64*U_STR + 2*32*W_STR + 128)

__global__ __launch_bounds__(256, 1) void lstm_k(const float* __restrict__ bias,
                                                 float* __restrict__ out) {
    extern __shared__ float sm[];
    float* ubuf = sm;                                 // [2][64][U_STR] h double buffer
    float* wsm  = sm + 2 * 64 * U_STR;                // [2][32][W_STR] w tiles
    float* satt = wsm + 2 * 32 * W_STR;               // [64]
    int*   ssrc = (int*)(satt + 64);                  // [64]

    int tid = threadIdx.x, lane = tid & 31, wrp = tid >> 5;
    int n0 = blockIdx.x * 64;

    // col offsets within a pass: jj = chl*4 + gate -> c = chl*128 + gate*32 + lane
    int co[8];
#pragma unroll
    for (int jj = 0; jj < 8; jj++) co[jj] = (jj >> 2) * 128 + (jj & 3) * 32 + lane;

    // bias registers
    float bc[2][8];
#pragma unroll
    for (int p = 0; p < 2; p++)
#pragma unroll
        for (int jj = 0; jj < 8; jj++) bc[p][jj] = g_bcat[p * 256 + co[jj]];

    // persistent cell state: creg[i][pass*2+chl] for dim (pass*2+chl)*32+lane, row wrp*8+i
    float creg[8][4];
#pragma unroll
    for (int i = 0; i < 8; i++)
#pragma unroll
        for (int q = 0; q < 4; q++) creg[i][q] = 0.0f;

    // init h buffer 0 to zero
    for (int idx = tid; idx < 64 * 128; idx += 256) {
        int r = idx >> 7, d = idx & 127;
        ubuf[r * U_STR + d] = 0.0f;
    }
    __syncthreads();

#pragma unroll 1
    for (int t = 0; t < DD; t++) {
        float* u  = ubuf + (t & 1) * 64 * U_STR;
        float* un = ubuf + ((t + 1) & 1) * 64 * U_STR;

        if (tid < 64) {
            int n = n0 + tid;
            if (n < NN) {
                ssrc[tid] = g_seqsrc[n * DD + t];
                satt[tid] = g_seqatt[n * DD + t];
            } else {
                ssrc[tid] = 0;
                satt[tid] = 0.0f;
            }
        }
        __syncthreads();

#pragma unroll
        for (int pass = 0; pass < 2; pass++) {
            float acc[8][8];
#pragma unroll
            for (int i = 0; i < 8; i++)
#pragma unroll
                for (int jj = 0; jj < 8; jj++) acc[i][jj] = 0.0f;

            // prologue: tile 0 -> buffer 0
            {
#pragma unroll
                for (int v = 0; v < 8; v++) {
                    int f4 = tid + v * 256;
                    int kk = f4 >> 6, c4 = f4 & 63;
                    float4 val = *((const float4*)(g_whh_pT + (size_t)kk * 512 + pass * 256) + c4);
                    *(float4*)(wsm + kk * W_STR + c4 * 4) = val;
                }
            }
            __syncthreads();

#pragma unroll
            for (int kt = 0; kt < 4; kt++) {
                float4 st[8];
                if (kt < 3) {
#pragma unroll
                    for (int v = 0; v < 8; v++) {
                        int f4 = tid + v * 256;
                        int kk = f4 >> 6, c4 = f4 & 63;
                        st[v] = *((const float4*)(g_whh_pT +
                                 (size_t)((kt + 1) * 32 + kk) * 512 + pass * 256) + c4);
                    }
                }
                const float* wb = wsm + (kt & 1) * 32 * W_STR;
                const float* ub = u + kt * 32;
#pragma unroll 4
                for (int kk = 0; kk < 32; kk++) {
                    float uv[8], wv[8];
#pragma unroll
                    for (int i = 0; i < 8; i++) uv[i] = ub[(wrp * 8 + i) * U_STR + kk];
#pragma unroll
                    for (int jj = 0; jj < 8; jj++) wv[jj] = wb[kk * W_STR + co[jj]];
#pragma unroll
                    for (int i = 0; i < 8; i++)
#pragma unroll
                        for (int jj = 0; jj < 8; jj++)
                            acc[i][jj] = fmaf(uv[i], wv[jj], acc[i][jj]);
                }
                if (kt < 3) {
                    float* db = wsm + ((kt + 1) & 1) * 32 * W_STR;
#pragma unroll
                    for (int v = 0; v < 8; v++) {
                        int f4 = tid + v * 256;
                        int kk = f4 >> 6, c4 = f4 & 63;
                        *(float4*)(db + kk * W_STR + c4 * 4) = st[v];
                    }
                }
                __syncthreads();
            }

            // x-contribution: att * P2[src] + bias (loads batched for MLP)
            float pv[8][8];
#pragma unroll
            for (int i = 0; i < 8; i++) {
                int s = ssrc[wrp * 8 + i];
                const float* pp = g_P2 + (size_t)s * 512 + pass * 256;
#pragma unroll
                for (int jj = 0; jj < 8; jj++) pv[i][jj] = pp[co[jj]];
            }
#pragma unroll
            for (int i = 0; i < 8; i++) {
                float a = satt[wrp * 8 + i];
#pragma unroll
                for (int jj = 0; jj < 8; jj++)
                    acc[i][jj] = fmaf(a, pv[i][jj], acc[i][jj] + bc[pass][jj]);
            }

            // gate activations + c/h update (c in registers, h -> un)
#pragma unroll
            for (int i = 0; i < 8; i++) {
#pragma unroll
                for (int chl = 0; chl < 2; chl++) {
                    float ig = sig_fast(acc[i][chl * 4 + 0]);
                    float fg = sig_fast(acc[i][chl * 4 + 1]);
                    float gg = tanh_fast(acc[i][chl * 4 + 2]);
                    float og = sig_fast(acc[i][chl * 4 + 3]);
                    int q = pass * 2 + chl;
                    float c_ = fmaf(fg, creg[i][q], ig * gg);
                    creg[i][q] = c_;
                    un[(wrp * 8 + i) * U_STR + q * 32 + lane] = og * tanh_fast(c_);
                }
            }
            __syncthreads();
        }
    }

    // epilogue: final h is in buffer (DD&1)==0
    __syncthreads();
    float* hf = ubuf;  // DD=16 even -> buffer 0
    for (int idx = tid; idx < 64 * 128; idx += 256) {
        int r = idx >> 7, d = idx & 127;
        int n = n0 + r;
        if (n < NN) {
            float v = hf[r * U_STR + d] + out[(size_t)n * 128 + d] + bias[d];
            out[(size_t)n * 128 + d] = (v >= 0.0f) ? v : 0.01f * v;
        }
    }
}

// ---------------- launch ----------------
extern "C" void kernel_launch(void* const* d_in, const int* in_sizes, int n_in,
                              void* d_out, int out_size) {
    const float* x    = (const float*)d_in[0];
    const float* Wp   = (const float*)d_in[1];
    const float* asrc = (const float*)d_in[2];
    const float* atrg = (const float*)d_in[3];
    const float* Wsk  = (const float*)d_in[4];
    const float* bias = (const float*)d_in[5];
    // d_in[6..9]: forward-direction weights, unused by the reference
    const float* wihb = (const float*)d_in[10];
    const float* whhb = (const float*)d_in[11];
    const float* bihb = (const float*)d_in[12];
    const float* bhhb = (const float*)d_in[13];
    const int*   ei   = (const int*)d_in[14];
    float* out = (float*)d_out;

    (void)in_sizes; (void)n_in; (void)out_size;

    cudaFuncSetAttribute(lstm_k, cudaFuncAttributeMaxDynamicSharedMemorySize,
                         LSTM_SM_FLOATS * (int)sizeof(float));

    prep_w_k<<<256, 256>>>(wihb, whhb, bihb, bhhb);
    gemm1_k<<<(NN + 63) / 64, 256>>>(x, Wp, Wsk, out);
    {
        dim3 g((NN + 63) / 64, 2);
        p2_k<<<g, 256>>>();
    }
    sdots_k<<<(NN * 32 + 255) / 256, 256>>>(asrc, atrg);
    initmax_k<<<1, 1>>>();
    scores_k<<<EE / 256, 256>>>(ei);
    sort_k<<<(NN + 255) / 256, 256>>>(ei);
    lstm_k<<<(NN + 63) / 64, 256, LSTM_SM_FLOATS * (int)sizeof(float)>>>(bias, out);
}

// round 7
// speedup vs baseline: 2.4361x; 1.1568x over previous
#include <cuda_runtime.h>
#include <math.h>

// ---------------- problem constants ----------------
#define NN    50000
#define FIN   256
#define FOUT  128
#define HH    128
#define DD    16
#define EE    (NN*DD)     // 800000
#define G4    512         // 4*H

// ---------------- scratch ----------------
__device__ float    g_proj[(size_t)NN*FOUT];   // 25.6MB
__device__ float    g_P2[(size_t)NN*G4];       // 102.4MB  P2 = proj @ w_ih^T (permuted cols)
__device__ float    g_ssrc[NN];
__device__ float    g_strg[NN];
__device__ float    g_scores[EE];
__device__ unsigned g_gmax;
__device__ int      g_seqsrc[EE];
__device__ float    g_seqatt[EE];
__device__ float    g_wih_p[G4*HH];            // permuted w_ih  [512 rows][128 k]  (row-major)
__device__ float    g_whh_pT[HH*G4];           // permuted w_hh  [128 k][512 cols]  (K-MAJOR)
__device__ float    g_bcat[G4];

// ---------------- helpers ----------------
__device__ __forceinline__ unsigned fenc(float f) {
    unsigned i = __float_as_uint(f);
    return (i & 0x80000000u) ? ~i : (i | 0x80000000u);
}
__device__ __forceinline__ float fdec(unsigned u) {
    return (u & 0x80000000u) ? __uint_as_float(u ^ 0x80000000u) : __uint_as_float(~u);
}
__device__ __forceinline__ float tanh_fast(float x) {
    float r;
    asm("tanh.approx.f32 %0, %1;" : "=f"(r) : "f"(x));
    return r;
}
__device__ __forceinline__ float sig_fast(float x) {
    return fmaf(tanh_fast(0.5f * x), 0.5f, 0.5f);
}
// packed f32x2 ops (Blackwell sm_103a)
typedef unsigned long long ull;
__device__ __forceinline__ ull pack2(float x, float y) {
    ull r; asm("mov.b64 %0, {%1,%2};" : "=l"(r) : "f"(x), "f"(y)); return r;
}
__device__ __forceinline__ float2 unpack2(ull v) {
    float2 r; asm("mov.b64 {%0,%1}, %2;" : "=f"(r.x), "=f"(r.y) : "l"(v)); return r;
}
__device__ __forceinline__ ull ffma2_(ull a, ull b, ull c) {
    ull d; asm("fma.rn.f32x2 %0, %1, %2, %3;" : "=l"(d) : "l"(a), "l"(b), "l"(c)); return d;
}
__device__ __forceinline__ ull add2_(ull a, ull b) {
    ull d; asm("add.rn.f32x2 %0, %1, %2;" : "=l"(d) : "l"(a), "l"(b)); return d;
}
// cp.async helpers
__device__ __forceinline__ void cp16(unsigned dst, const void* src) {
    asm volatile("cp.async.ca.shared.global [%0], [%1], 16;" :: "r"(dst), "l"(src));
}
__device__ __forceinline__ void cp_commit() { asm volatile("cp.async.commit_group;"); }
template <int N>
__device__ __forceinline__ void cp_wait() { asm volatile("cp.async.wait_group %0;" :: "n"(N)); }

// ---------------- kernel: build permuted weights ----------------
__global__ void prep_w_k(const float* __restrict__ wih, const float* __restrict__ whh,
                         const float* __restrict__ bih, const float* __restrict__ bhh) {
    int idx = blockIdx.x * blockDim.x + threadIdx.x;   // 0..65535
    int R = idx >> 7;
    int k = idx & 127;
    int ch = R >> 7, c = R & 127;
    int gate = c >> 5, dd = c & 31;
    int grow = gate * 128 + ch * 32 + dd;
    g_wih_p[R * 128 + k]  = wih[grow * 128 + k];
    g_whh_pT[k * 512 + R] = whh[grow * 128 + k];
    if (k == 0) g_bcat[R] = bih[grow] + bhh[grow];
}

// ---------------- kernel: proj + skip fused GEMM (FFMA2, row-paired) ----------------
__global__ __launch_bounds__(256) void gemm1_k(const float* __restrict__ x,
                                               const float* __restrict__ Wp,
                                               const float* __restrict__ Wsk,
                                               float* __restrict__ out) {
    __shared__ float xs2[32 * 66];    // [kk][row] transposed, pad 2
    __shared__ float ws[256 * 33];    // [col][kk]
    int tid = threadIdx.x, lane = tid & 31, wrp = tid >> 5;
    int n0 = blockIdx.x * 64;
    ull accp[4][8];
#pragma unroll
    for (int rp = 0; rp < 4; rp++)
#pragma unroll
        for (int j = 0; j < 8; j++) accp[rp][j] = 0ull;

    for (int k0 = 0; k0 < 256; k0 += 32) {
        __syncthreads();
#pragma unroll
        for (int v = 0; v < 8; v++) {
            int idx = tid + v * 256;
            int r = idx >> 5, kk = idx & 31;
            int n = n0 + r;
            xs2[kk * 66 + r] = (n < NN) ? x[(size_t)n * 256 + k0 + kk] : 0.0f;
        }
#pragma unroll
        for (int v = 0; v < 32; v++) {
            int idx = tid + v * 256;
            int c = idx >> 5, kk = idx & 31;
            ws[c * 33 + kk] = (c < 128) ? Wp[c * 256 + k0 + kk]
                                        : Wsk[(c - 128) * 256 + k0 + kk];
        }
        __syncthreads();
#pragma unroll 4
        for (int kk = 0; kk < 32; kk++) {
            ull uvp[4], wvp[8];
#pragma unroll
            for (int rp = 0; rp < 4; rp++) {
                float2 u2 = *(const float2*)(xs2 + kk * 66 + wrp * 8 + 2 * rp);
                uvp[rp] = pack2(u2.x, u2.y);
            }
#pragma unroll
            for (int j = 0; j < 8; j++) {
                float wv = ws[(j * 32 + lane) * 33 + kk];
                wvp[j] = pack2(wv, wv);
            }
#pragma unroll
            for (int rp = 0; rp < 4; rp++)
#pragma unroll
                for (int j = 0; j < 8; j++)
                    accp[rp][j] = ffma2_(uvp[rp], wvp[j], accp[rp][j]);
        }
    }
#pragma unroll
    for (int rp = 0; rp < 4; rp++) {
        int n = n0 + wrp * 8 + 2 * rp;
#pragma unroll
        for (int j = 0; j < 8; j++) {
            float2 res = unpack2(accp[rp][j]);
            int c = j * 32 + lane;
            if (n < NN) {
                if (c < 128) g_proj[(size_t)n * 128 + c] = res.x;
                else         out[(size_t)n * 128 + (c - 128)] = res.x;
            }
            if (n + 1 < NN) {
                if (c < 128) g_proj[(size_t)(n + 1) * 128 + c] = res.y;
                else         out[(size_t)(n + 1) * 128 + (c - 128)] = res.y;
            }
        }
    }
}

// ---------------- kernel: P2 = proj @ w_ih_p^T (FFMA2, row-paired) ----------
__global__ __launch_bounds__(256) void p2_k() {
    __shared__ float xs2[32 * 66];
    __shared__ float ws[256 * 33];
    int tid = threadIdx.x, lane = tid & 31, wrp = tid >> 5;
    int n0 = blockIdx.x * 64;
    int coff = blockIdx.y * 256;
    ull accp[4][8];
#pragma unroll
    for (int rp = 0; rp < 4; rp++)
#pragma unroll
        for (int j = 0; j < 8; j++) accp[rp][j] = 0ull;

    for (int k0 = 0; k0 < 128; k0 += 32) {
        __syncthreads();
#pragma unroll
        for (int v = 0; v < 8; v++) {
            int idx = tid + v * 256;
            int r = idx >> 5, kk = idx & 31;
            int n = n0 + r;
            xs2[kk * 66 + r] = (n < NN) ? g_proj[(size_t)n * 128 + k0 + kk] : 0.0f;
        }
#pragma unroll
        for (int v = 0; v < 32; v++) {
            int idx = tid + v * 256;
            int c = idx >> 5, kk = idx & 31;
            ws[c * 33 + kk] = g_wih_p[(coff + c) * 128 + k0 + kk];
        }
        __syncthreads();
#pragma unroll 4
        for (int kk = 0; kk < 32; kk++) {
            ull uvp[4], wvp[8];
#pragma unroll
            for (int rp = 0; rp < 4; rp++) {
                float2 u2 = *(const float2*)(xs2 + kk * 66 + wrp * 8 + 2 * rp);
                uvp[rp] = pack2(u2.x, u2.y);
            }
#pragma unroll
            for (int j = 0; j < 8; j++) {
                float wv = ws[(j * 32 + lane) * 33 + kk];
                wvp[j] = pack2(wv, wv);
            }
#pragma unroll
            for (int rp = 0; rp < 4; rp++)
#pragma unroll
                for (int j = 0; j < 8; j++)
                    accp[rp][j] = ffma2_(uvp[rp], wvp[j], accp[rp][j]);
        }
    }
#pragma unroll
    for (int rp = 0; rp < 4; rp++) {
        int n = n0 + wrp * 8 + 2 * rp;
#pragma unroll
        for (int j = 0; j < 8; j++) {
            float2 res = unpack2(accp[rp][j]);
            int c = coff + j * 32 + lane;
            if (n < NN)     g_P2[(size_t)n * 512 + c] = res.x;
            if (n + 1 < NN) g_P2[(size_t)(n + 1) * 512 + c] = res.y;
        }
    }
}

// ---------------- kernel: per-node attention dots ----------------
__global__ void sdots_k(const float* __restrict__ as, const float* __restrict__ at) {
    int gtid = blockIdx.x * blockDim.x + threadIdx.x;
    int warp = gtid >> 5;
    int lane = gtid & 31;
    if (warp >= NN) return;
    const float* p = g_proj + (size_t)warp * 128;
    float s1 = 0.0f, s2 = 0.0f;
#pragma unroll
    for (int d = lane; d < 128; d += 32) {
        float v = p[d];
        s1 = fmaf(v, as[d], s1);
        s2 = fmaf(v, at[d], s2);
    }
#pragma unroll
    for (int o = 16; o; o >>= 1) {
        s1 += __shfl_xor_sync(0xffffffffu, s1, o);
        s2 += __shfl_xor_sync(0xffffffffu, s2, o);
    }
    if (lane == 0) { g_ssrc[warp] = s1; g_strg[warp] = s2; }
}

__global__ void initmax_k() { g_gmax = 0u; }

// ---------------- kernel: edge scores + global max ----------------
__global__ void scores_k(const int* __restrict__ ei) {
    int e = blockIdx.x * blockDim.x + threadIdx.x;
    int s = ei[e];
    int t = ei[EE + e];
    float sc = g_ssrc[s] + g_strg[t];
    sc = (sc >= 0.0f) ? sc : 0.2f * sc;
    g_scores[e] = sc;
    float m = sc;
#pragma unroll
    for (int o = 16; o; o >>= 1) m = fmaxf(m, __shfl_xor_sync(0xffffffffu, m, o));
    __shared__ float wm[8];
    int lane = threadIdx.x & 31, wid = threadIdx.x >> 5;
    if (lane == 0) wm[wid] = m;
    __syncthreads();
    if (threadIdx.x == 0) {
        float mm = wm[0];
#pragma unroll
        for (int w = 1; w < 8; w++) mm = fmaxf(mm, wm[w]);
        atomicMax(&g_gmax, fenc(mm));
    }
}

// ---------------- kernel: softmax + stable sort ----------------
__global__ void sort_k(const int* __restrict__ ei) {
    int n = blockIdx.x * blockDim.x + threadIdx.x;
    if (n >= NN) return;
    float gmax = fdec(g_gmax);
    float ev[DD], srt[DD];
    int idx[DD];
    float denom = 0.0f;
#pragma unroll
    for (int j = 0; j < DD; j++) {
        float e = expf(g_scores[n * DD + j] - gmax);
        ev[j] = e;
        denom += e;
    }
    denom += 1e-16f;
    for (int j = 0; j < DD; j++) {
        float key = ev[j];
        int pos = j;
        while (pos > 0 && srt[pos - 1] <= key) {
            srt[pos] = srt[pos - 1];
            idx[pos] = idx[pos - 1];
            pos--;
        }
        srt[pos] = key;
        idx[pos] = j;
    }
    float inv = 1.0f / denom;
#pragma unroll
    for (int t = 0; t < DD; t++) {
        int j = idx[t];
        g_seqsrc[n * DD + t] = ei[n * DD + j];
        g_seqatt[n * DD + t] = srt[t] * inv;
    }
}

// ---------------- kernel: backward LSTM, FFMA2, c in registers ----------------
// 64 nodes / block, 256 threads (8 warps). warp owns 8 rows; lane owns adjacent
// dim pairs: hl = lane>>4 (chunk within pass), p = lane&15 -> dims 2p, 2p+1.
// Per pass (256 gate cols): accp[8 rows][4 gates] packed f32x2 pairs.
#define U_STR 132
#define W_STR 260
#define LSTM_SM_FLOATS (2*64*U_STR + 2*32*W_STR + 128)

__global__ __launch_bounds__(256, 1) void lstm_k(const float* __restrict__ bias,
                                                 float* __restrict__ out) {
    extern __shared__ float sm[];
    float* ubuf = sm;                                 // [2][64][U_STR] h double buffer
    float* wsm  = sm + 2 * 64 * U_STR;                // [2][32][W_STR] w tiles
    float* satt = wsm + 2 * 32 * W_STR;               // [64]
    int*   ssrc = (int*)(satt + 64);                  // [64]

    int tid = threadIdx.x, lane = tid & 31, wrp = tid >> 5;
    int hl = lane >> 4, p = lane & 15;
    int n0 = blockIdx.x * 64;
    unsigned wsm_s = (unsigned)__cvta_generic_to_shared(wsm);

    // col offsets within a pass: gate g -> col = hl*128 + g*32 + 2p (pair)
    int co[4];
#pragma unroll
    for (int g = 0; g < 4; g++) co[g] = hl * 128 + g * 32 + 2 * p;

    // bias pairs
    ull bcp[2][4];
#pragma unroll
    for (int ps = 0; ps < 2; ps++)
#pragma unroll
        for (int g = 0; g < 4; g++) {
            float2 b2 = *(const float2*)(g_bcat + ps * 256 + co[g]);
            bcp[ps][g] = pack2(b2.x, b2.y);
        }

    // persistent cell state: creg2[row][pass] = c for dims (pass*2+hl)*32 + {2p,2p+1}
    float2 creg2[8][2];
#pragma unroll
    for (int i = 0; i < 8; i++)
#pragma unroll
        for (int ps = 0; ps < 2; ps++) creg2[i][ps] = make_float2(0.0f, 0.0f);

    // init h buffer 0 to zero
    for (int idx = tid; idx < 64 * 128; idx += 256) {
        int r = idx >> 7, d = idx & 127;
        ubuf[r * U_STR + d] = 0.0f;
    }
    __syncthreads();

#pragma unroll 1
    for (int t = 0; t < DD; t++) {
        float* u  = ubuf + (t & 1) * 64 * U_STR;
        float* un = ubuf + ((t + 1) & 1) * 64 * U_STR;

        if (tid < 64) {
            int n = n0 + tid;
            if (n < NN) {
                ssrc[tid] = g_seqsrc[n * DD + t];
                satt[tid] = g_seqatt[n * DD + t];
            } else {
                ssrc[tid] = 0;
                satt[tid] = 0.0f;
            }
        }
        __syncthreads();

#pragma unroll 1
        for (int ps = 0; ps < 2; ps++) {
            ull accp[8][4];
#pragma unroll
            for (int i = 0; i < 8; i++)
#pragma unroll
                for (int g = 0; g < 4; g++) accp[i][g] = 0ull;

            // prologue: async-stage tile 0 -> buffer 0
#pragma unroll
            for (int v = 0; v < 8; v++) {
                int f4 = tid + v * 256;
                int kk = f4 >> 6, c4 = f4 & 63;
                cp16(wsm_s + (kk * W_STR + c4 * 4) * 4,
                     g_whh_pT + (size_t)kk * 512 + ps * 256 + c4 * 4);
            }
            cp_commit();

#pragma unroll 1
            for (int kt = 0; kt < 4; kt++) {
                if (kt < 3) {
                    unsigned db = wsm_s + (((kt + 1) & 1) * 32 * W_STR) * 4;
#pragma unroll
                    for (int v = 0; v < 8; v++) {
                        int f4 = tid + v * 256;
                        int kk = f4 >> 6, c4 = f4 & 63;
                        cp16(db + (kk * W_STR + c4 * 4) * 4,
                             g_whh_pT + (size_t)((kt + 1) * 32 + kk) * 512 + ps * 256 + c4 * 4);
                    }
                    cp_commit();
                    cp_wait<1>();
                } else {
                    cp_wait<0>();
                }
                __syncthreads();

                const float* wb = wsm + (kt & 1) * 32 * W_STR;
                const float* ub = u + kt * 32;
#pragma unroll 4
                for (int kk2 = 0; kk2 < 16; kk2++) {
                    float2 uk[8];
#pragma unroll
                    for (int i = 0; i < 8; i++)
                        uk[i] = *(const float2*)(ub + (wrp * 8 + i) * U_STR + 2 * kk2);
#pragma unroll
                    for (int sub = 0; sub < 2; sub++) {
                        ull wvp[4];
#pragma unroll
                        for (int g = 0; g < 4; g++) {
                            float2 w2 = *(const float2*)(wb + (2 * kk2 + sub) * W_STR + co[g]);
                            wvp[g] = pack2(w2.x, w2.y);
                        }
#pragma unroll
                        for (int i = 0; i < 8; i++) {
                            float us = sub ? uk[i].y : uk[i].x;
                            ull up = pack2(us, us);
#pragma unroll
                            for (int g = 0; g < 4; g++)
                                accp[i][g] = ffma2_(up, wvp[g], accp[i][g]);
                        }
                    }
                }
                __syncthreads();
            }

            // x-contribution: acc = acc + bias + att * P2[src]  (batched 4 rows)
#pragma unroll
            for (int half = 0; half < 2; half++) {
                ull pvp[4][4];
#pragma unroll
                for (int i2 = 0; i2 < 4; i2++) {
                    int s = ssrc[wrp * 8 + half * 4 + i2];
                    const float* pp = g_P2 + (size_t)s * 512 + ps * 256;
#pragma unroll
                    for (int g = 0; g < 4; g++) {
                        float2 v2 = *(const float2*)(pp + co[g]);
                        pvp[i2][g] = pack2(v2.x, v2.y);
                    }
                }
#pragma unroll
                for (int i2 = 0; i2 < 4; i2++) {
                    int i = half * 4 + i2;
                    float a = satt[wrp * 8 + i];
                    ull ap = pack2(a, a);
#pragma unroll
                    for (int g = 0; g < 4; g++)
                        accp[i][g] = ffma2_(ap, pvp[i2][g], add2_(accp[i][g], bcp[ps][g]));
                }
            }

            // gate activations + c/h update
            int hoff = (ps * 2 + hl) * 32 + 2 * p;
#pragma unroll
            for (int i = 0; i < 8; i++) {
                float2 iv = unpack2(accp[i][0]);
                float2 fv = unpack2(accp[i][1]);
                float2 gv = unpack2(accp[i][2]);
                float2 ov = unpack2(accp[i][3]);
                float2 cp2 = creg2[i][ps];
                float c0 = fmaf(sig_fast(fv.x), cp2.x, sig_fast(iv.x) * tanh_fast(gv.x));
                float c1 = fmaf(sig_fast(fv.y), cp2.y, sig_fast(iv.y) * tanh_fast(gv.y));
                creg2[i][ps] = make_float2(c0, c1);
                float2 hh = make_float2(sig_fast(ov.x) * tanh_fast(c0),
                                        sig_fast(ov.y) * tanh_fast(c1));
                *(float2*)(un + (wrp * 8 + i) * U_STR + hoff) = hh;
            }
            __syncthreads();
        }
    }

    // epilogue: DD even -> final h in buffer 0
    float* hf = ubuf;
    for (int idx = tid; idx < 64 * 128; idx += 256) {
        int r = idx >> 7, d = idx & 127;
        int n = n0 + r;
        if (n < NN) {
            float v = hf[r * U_STR + d] + out[(size_t)n * 128 + d] + bias[d];
            out[(size_t)n * 128 + d] = (v >= 0.0f) ? v : 0.01f * v;
        }
    }
}

// ---------------- launch ----------------
extern "C" void kernel_launch(void* const* d_in, const int* in_sizes, int n_in,
                              void* d_out, int out_size) {
    const float* x    = (const float*)d_in[0];
    const float* Wp   = (const float*)d_in[1];
    const float* asrc = (const float*)d_in[2];
    const float* atrg = (const float*)d_in[3];
    const float* Wsk  = (const float*)d_in[4];
    const float* bias = (const float*)d_in[5];
    // d_in[6..9]: forward-direction weights, unused by the reference
    const float* wihb = (const float*)d_in[10];
    const float* whhb = (const float*)d_in[11];
    const float* bihb = (const float*)d_in[12];
    const float* bhhb = (const float*)d_in[13];
    const int*   ei   = (const int*)d_in[14];
    float* out = (float*)d_out;

    (void)in_sizes; (void)n_in; (void)out_size;

    cudaFuncSetAttribute(lstm_k, cudaFuncAttributeMaxDynamicSharedMemorySize,
                         LSTM_SM_FLOATS * (int)sizeof(float));

    prep_w_k<<<256, 256>>>(wihb, whhb, bihb, bhhb);
    gemm1_k<<<(NN + 63) / 64, 256>>>(x, Wp, Wsk, out);
    {
        dim3 g((NN + 63) / 64, 2);
        p2_k<<<g, 256>>>();
    }
    sdots_k<<<(NN * 32 + 255) / 256, 256>>>(asrc, atrg);
    initmax_k<<<1, 1>>>();
    scores_k<<<EE / 256, 256>>>(ei);
    sort_k<<<(NN + 255) / 256, 256>>>(ei);
    lstm_k<<<(NN + 63) / 64, 256, LSTM_SM_FLOATS * (int)sizeof(float)>>>(bias, out);
}

// round 8
// speedup vs baseline: 2.7298x; 1.1206x over previous
#include <cuda_runtime.h>
#include <math.h>

// ---------------- problem constants ----------------
#define NN    50000
#define FIN   256
#define FOUT  128
#define HH    128
#define DD    16
#define EE    (NN*DD)     // 800000
#define G4    512         // 4*H

// ---------------- scratch ----------------
__device__ float    g_proj[(size_t)NN*FOUT];   // 25.6MB
__device__ float    g_P2[(size_t)NN*G4];       // 102.4MB  P2 = proj @ w_ih^T (permuted cols)
__device__ float    g_ssrc[NN];
__device__ float    g_strg[NN];
__device__ float    g_scores[EE];
__device__ unsigned g_gmax;
__device__ int      g_seqsrc[EE];
__device__ float    g_seqatt[EE];
__device__ float    g_wih_p[G4*HH];            // permuted w_ih  [512 rows][128 k]  (row-major)
__device__ float    g_whh_pT[HH*G4];           // permuted w_hh  [128 k][512 cols]  (K-MAJOR)
__device__ float    g_bcat[G4];

// ---------------- helpers ----------------
__device__ __forceinline__ unsigned fenc(float f) {
    unsigned i = __float_as_uint(f);
    return (i & 0x80000000u) ? ~i : (i | 0x80000000u);
}
__device__ __forceinline__ float fdec(unsigned u) {
    return (u & 0x80000000u) ? __uint_as_float(u ^ 0x80000000u) : __uint_as_float(~u);
}
__device__ __forceinline__ float tanh_fast(float x) {
    float r;
    asm("tanh.approx.f32 %0, %1;" : "=f"(r) : "f"(x));
    return r;
}
__device__ __forceinline__ float sig_fast(float x) {
    return fmaf(tanh_fast(0.5f * x), 0.5f, 0.5f);
}
// packed f32x2 ops (Blackwell sm_103a)
typedef unsigned long long ull;
__device__ __forceinline__ ull pack2(float x, float y) {
    ull r; asm("mov.b64 %0, {%1,%2};" : "=l"(r) : "f"(x), "f"(y)); return r;
}
__device__ __forceinline__ float2 unpack2(ull v) {
    float2 r; asm("mov.b64 {%0,%1}, %2;" : "=f"(r.x), "=f"(r.y) : "l"(v)); return r;
}
__device__ __forceinline__ ull ffma2_(ull a, ull b, ull c) {
    ull d; asm("fma.rn.f32x2 %0, %1, %2, %3;" : "=l"(d) : "l"(a), "l"(b), "l"(c)); return d;
}
__device__ __forceinline__ ull add2_(ull a, ull b) {
    ull d; asm("add.rn.f32x2 %0, %1, %2;" : "=l"(d) : "l"(a), "l"(b)); return d;
}
// cp.async helpers
__device__ __forceinline__ void cp16(unsigned dst, const void* src) {
    asm volatile("cp.async.ca.shared.global [%0], [%1], 16;" :: "r"(dst), "l"(src));
}
__device__ __forceinline__ void cp_commit() { asm volatile("cp.async.commit_group;"); }
template <int N>
__device__ __forceinline__ void cp_wait() { asm volatile("cp.async.wait_group %0;" :: "n"(N)); }

// ---------------- kernel: build permuted weights ----------------
__global__ void prep_w_k(const float* __restrict__ wih, const float* __restrict__ whh,
                         const float* __restrict__ bih, const float* __restrict__ bhh) {
    int idx = blockIdx.x * blockDim.x + threadIdx.x;   // 0..65535
    int R = idx >> 7;
    int k = idx & 127;
    int ch = R >> 7, c = R & 127;
    int gate = c >> 5, dd = c & 31;
    int grow = gate * 128 + ch * 32 + dd;
    g_wih_p[R * 128 + k]  = wih[grow * 128 + k];
    g_whh_pT[k * 512 + R] = whh[grow * 128 + k];
    if (k == 0) g_bcat[R] = bih[grow] + bhh[grow];
}

// ---------------- kernel: proj + skip fused GEMM (FFMA2, row-paired) ----------------
__global__ __launch_bounds__(256) void gemm1_k(const float* __restrict__ x,
                                               const float* __restrict__ Wp,
                                               const float* __restrict__ Wsk,
                                               float* __restrict__ out) {
    __shared__ float xs2[32 * 66];    // [kk][row] transposed, pad 2
    __shared__ float ws[256 * 33];    // [col][kk]
    int tid = threadIdx.x, lane = tid & 31, wrp = tid >> 5;
    int n0 = blockIdx.x * 64;
    ull accp[4][8];
#pragma unroll
    for (int rp = 0; rp < 4; rp++)
#pragma unroll
        for (int j = 0; j < 8; j++) accp[rp][j] = 0ull;

    for (int k0 = 0; k0 < 256; k0 += 32) {
        __syncthreads();
#pragma unroll
        for (int v = 0; v < 8; v++) {
            int idx = tid + v * 256;
            int r = idx >> 5, kk = idx & 31;
            int n = n0 + r;
            xs2[kk * 66 + r] = (n < NN) ? x[(size_t)n * 256 + k0 + kk] : 0.0f;
        }
#pragma unroll
        for (int v = 0; v < 32; v++) {
            int idx = tid + v * 256;
            int c = idx >> 5, kk = idx & 31;
            ws[c * 33 + kk] = (c < 128) ? Wp[c * 256 + k0 + kk]
                                        : Wsk[(c - 128) * 256 + k0 + kk];
        }
        __syncthreads();
#pragma unroll 4
        for (int kk = 0; kk < 32; kk++) {
            ull uvp[4], wvp[8];
#pragma unroll
            for (int rp = 0; rp < 4; rp++) {
                float2 u2 = *(const float2*)(xs2 + kk * 66 + wrp * 8 + 2 * rp);
                uvp[rp] = pack2(u2.x, u2.y);
            }
#pragma unroll
            for (int j = 0; j < 8; j++) {
                float wv = ws[(j * 32 + lane) * 33 + kk];
                wvp[j] = pack2(wv, wv);
            }
#pragma unroll
            for (int rp = 0; rp < 4; rp++)
#pragma unroll
                for (int j = 0; j < 8; j++)
                    accp[rp][j] = ffma2_(uvp[rp], wvp[j], accp[rp][j]);
        }
    }
#pragma unroll
    for (int rp = 0; rp < 4; rp++) {
        int n = n0 + wrp * 8 + 2 * rp;
#pragma unroll
        for (int j = 0; j < 8; j++) {
            float2 res = unpack2(accp[rp][j]);
            int c = j * 32 + lane;
            if (n < NN) {
                if (c < 128) g_proj[(size_t)n * 128 + c] = res.x;
                else         out[(size_t)n * 128 + (c - 128)] = res.x;
            }
            if (n + 1 < NN) {
                if (c < 128) g_proj[(size_t)(n + 1) * 128 + c] = res.y;
                else         out[(size_t)(n + 1) * 128 + (c - 128)] = res.y;
            }
        }
    }
}

// ---------------- kernel: P2 = proj @ w_ih_p^T (FFMA2, row-paired) ----------
__global__ __launch_bounds__(256) void p2_k() {
    __shared__ float xs2[32 * 66];
    __shared__ float ws[256 * 33];
    int tid = threadIdx.x, lane = tid & 31, wrp = tid >> 5;
    int n0 = blockIdx.x * 64;
    int coff = blockIdx.y * 256;
    ull accp[4][8];
#pragma unroll
    for (int rp = 0; rp < 4; rp++)
#pragma unroll
        for (int j = 0; j < 8; j++) accp[rp][j] = 0ull;

    for (int k0 = 0; k0 < 128; k0 += 32) {
        __syncthreads();
#pragma unroll
        for (int v = 0; v < 8; v++) {
            int idx = tid + v * 256;
            int r = idx >> 5, kk = idx & 31;
            int n = n0 + r;
            xs2[kk * 66 + r] = (n < NN) ? g_proj[(size_t)n * 128 + k0 + kk] : 0.0f;
        }
#pragma unroll
        for (int v = 0; v < 32; v++) {
            int idx = tid + v * 256;
            int c = idx >> 5, kk = idx & 31;
            ws[c * 33 + kk] = g_wih_p[(coff + c) * 128 + k0 + kk];
        }
        __syncthreads();
#pragma unroll 4
        for (int kk = 0; kk < 32; kk++) {
            ull uvp[4], wvp[8];
#pragma unroll
            for (int rp = 0; rp < 4; rp++) {
                float2 u2 = *(const float2*)(xs2 + kk * 66 + wrp * 8 + 2 * rp);
                uvp[rp] = pack2(u2.x, u2.y);
            }
#pragma unroll
            for (int j = 0; j < 8; j++) {
                float wv = ws[(j * 32 + lane) * 33 + kk];
                wvp[j] = pack2(wv, wv);
            }
#pragma unroll
            for (int rp = 0; rp < 4; rp++)
#pragma unroll
                for (int j = 0; j < 8; j++)
                    accp[rp][j] = ffma2_(uvp[rp], wvp[j], accp[rp][j]);
        }
    }
#pragma unroll
    for (int rp = 0; rp < 4; rp++) {
        int n = n0 + wrp * 8 + 2 * rp;
#pragma unroll
        for (int j = 0; j < 8; j++) {
            float2 res = unpack2(accp[rp][j]);
            int c = coff + j * 32 + lane;
            if (n < NN)     g_P2[(size_t)n * 512 + c] = res.x;
            if (n + 1 < NN) g_P2[(size_t)(n + 1) * 512 + c] = res.y;
        }
    }
}

// ---------------- kernel: per-node attention dots ----------------
__global__ void sdots_k(const float* __restrict__ as, const float* __restrict__ at) {
    int gtid = blockIdx.x * blockDim.x + threadIdx.x;
    int warp = gtid >> 5;
    int lane = gtid & 31;
    if (warp >= NN) return;
    const float* p = g_proj + (size_t)warp * 128;
    float s1 = 0.0f, s2 = 0.0f;
#pragma unroll
    for (int d = lane; d < 128; d += 32) {
        float v = p[d];
        s1 = fmaf(v, as[d], s1);
        s2 = fmaf(v, at[d], s2);
    }
#pragma unroll
    for (int o = 16; o; o >>= 1) {
        s1 += __shfl_xor_sync(0xffffffffu, s1, o);
        s2 += __shfl_xor_sync(0xffffffffu, s2, o);
    }
    if (lane == 0) { g_ssrc[warp] = s1; g_strg[warp] = s2; }
}

__global__ void initmax_k() { g_gmax = 0u; }

// ---------------- kernel: edge scores + global max ----------------
__global__ void scores_k(const int* __restrict__ ei) {
    int e = blockIdx.x * blockDim.x + threadIdx.x;
    int s = ei[e];
    int t = ei[EE + e];
    float sc = g_ssrc[s] + g_strg[t];
    sc = (sc >= 0.0f) ? sc : 0.2f * sc;
    g_scores[e] = sc;
    float m = sc;
#pragma unroll
    for (int o = 16; o; o >>= 1) m = fmaxf(m, __shfl_xor_sync(0xffffffffu, m, o));
    __shared__ float wm[8];
    int lane = threadIdx.x & 31, wid = threadIdx.x >> 5;
    if (lane == 0) wm[wid] = m;
    __syncthreads();
    if (threadIdx.x == 0) {
        float mm = wm[0];
#pragma unroll
        for (int w = 1; w < 8; w++) mm = fmaxf(mm, wm[w]);
        atomicMax(&g_gmax, fenc(mm));
    }
}

// ---------------- kernel: softmax + stable sort ----------------
__global__ void sort_k(const int* __restrict__ ei) {
    int n = blockIdx.x * blockDim.x + threadIdx.x;
    if (n >= NN) return;
    float gmax = fdec(g_gmax);
    float ev[DD], srt[DD];
    int idx[DD];
    float denom = 0.0f;
#pragma unroll
    for (int j = 0; j < DD; j++) {
        float e = expf(g_scores[n * DD + j] - gmax);
        ev[j] = e;
        denom += e;
    }
    denom += 1e-16f;
    for (int j = 0; j < DD; j++) {
        float key = ev[j];
        int pos = j;
        while (pos > 0 && srt[pos - 1] <= key) {
            srt[pos] = srt[pos - 1];
            idx[pos] = idx[pos - 1];
            pos--;
        }
        srt[pos] = key;
        idx[pos] = j;
    }
    float inv = 1.0f / denom;
#pragma unroll
    for (int t = 0; t < DD; t++) {
        int j = idx[t];
        g_seqsrc[n * DD + t] = ei[n * DD + j];
        g_seqatt[n * DD + t] = srt[t] * inv;
    }
}

// ---------------- kernel: backward LSTM, FFMA2, merged single-pass ----------------
// 64 nodes / block, 256 threads (8 warps). Warp owns 8 rows; lane (hl=lane>>4,
// p=lane&15) owns hidden-dim pairs {2p,2p+1} of chunks (hl) and (hl+2).
// Per timestep: one GEMM pass over all 512 gate cols (accp[8][8] f32x2 pairs),
// h updated in place, c in registers. t=0 GEMM skipped (h=0).
#define U_STR 132
#define KT 32
#define W_STR 520
#define LSTM_SM_FLOATS (64*U_STR + 2*KT*W_STR + 160)

__global__ __launch_bounds__(256, 1) void lstm_k(const float* __restrict__ bias,
                                                 float* __restrict__ out) {
    extern __shared__ float sm[];
    float* u    = sm;                          // [64][U_STR] h (in-place)
    float* wsm  = sm + 64 * U_STR;             // [2][KT][W_STR] w tiles
    float* satt = wsm + 2 * KT * W_STR;        // [64]
    int*   ssrc = (int*)(satt + 64);           // [64]

    int tid = threadIdx.x, lane = tid & 31, wrp = tid >> 5;
    int hl = lane >> 4, p = lane & 15;
    int n0 = blockIdx.x * 64;
    unsigned wsm_s = (unsigned)__cvta_generic_to_shared(wsm);

    // col offsets: jj = cs*4 + g -> col = (hl+2cs)*128 + g*32 + 2p
    int co[8];
#pragma unroll
    for (int jj = 0; jj < 8; jj++)
        co[jj] = (hl + 2 * (jj >> 2)) * 128 + (jj & 3) * 32 + 2 * p;

    // bias pairs
    ull bcp[8];
#pragma unroll
    for (int jj = 0; jj < 8; jj++) {
        float2 b2 = *(const float2*)(g_bcat + co[jj]);
        bcp[jj] = pack2(b2.x, b2.y);
    }

    // cell state: creg2[row][cs] = c for dims (hl+2cs)*32 + {2p,2p+1}
    float2 creg2[8][2];
#pragma unroll
    for (int i = 0; i < 8; i++)
#pragma unroll
        for (int cs = 0; cs < 2; cs++) creg2[i][cs] = make_float2(0.0f, 0.0f);

#pragma unroll 1
    for (int t = 0; t < DD; t++) {
        if (tid < 64) {
            int n = n0 + tid;
            if (n < NN) {
                ssrc[tid] = g_seqsrc[n * DD + t];
                satt[tid] = g_seqatt[n * DD + t];
            } else {
                ssrc[tid] = 0;
                satt[tid] = 0.0f;
            }
        }
        __syncthreads();

        ull accp[8][8];
#pragma unroll
        for (int i = 0; i < 8; i++)
#pragma unroll
            for (int jj = 0; jj < 8; jj++) accp[i][jj] = 0ull;

        if (t > 0) {
            // prologue: stage tile 0 (k 0..31) into buffer 0
#pragma unroll
            for (int v = 0; v < 16; v++) {
                int f4 = tid + v * 256;
                int kk = f4 >> 7, c4 = f4 & 127;
                cp16(wsm_s + (kk * W_STR + c4 * 4) * 4,
                     g_whh_pT + (size_t)kk * 512 + c4 * 4);
            }
            cp_commit();

#pragma unroll 1
            for (int kt = 0; kt < 4; kt++) {
                if (kt < 3) {
                    unsigned db = wsm_s + (((kt + 1) & 1) * KT * W_STR) * 4;
#pragma unroll
                    for (int v = 0; v < 16; v++) {
                        int f4 = tid + v * 256;
                        int kk = f4 >> 7, c4 = f4 & 127;
                        cp16(db + (kk * W_STR + c4 * 4) * 4,
                             g_whh_pT + (size_t)((kt + 1) * KT + kk) * 512 + c4 * 4);
                    }
                    cp_commit();
                    cp_wait<1>();
                } else {
                    cp_wait<0>();
                }
                __syncthreads();

                const float* wb = wsm + (kt & 1) * KT * W_STR;
                const float* ub = u + kt * KT;
#pragma unroll 4
                for (int kk2 = 0; kk2 < KT / 2; kk2++) {
                    float2 uk[8];
#pragma unroll
                    for (int i = 0; i < 8; i++)
                        uk[i] = *(const float2*)(ub + (wrp * 8 + i) * U_STR + 2 * kk2);
#pragma unroll
                    for (int sub = 0; sub < 2; sub++) {
                        ull wvp[8];
#pragma unroll
                        for (int jj = 0; jj < 8; jj++) {
                            float2 w2 = *(const float2*)(wb + (2 * kk2 + sub) * W_STR + co[jj]);
                            wvp[jj] = pack2(w2.x, w2.y);
                        }
#pragma unroll
                        for (int i = 0; i < 8; i++) {
                            float us = sub ? uk[i].y : uk[i].x;
                            ull up = pack2(us, us);
#pragma unroll
                            for (int jj = 0; jj < 8; jj++)
                                accp[i][jj] = ffma2_(up, wvp[jj], accp[i][jj]);
                        }
                    }
                }
                __syncthreads();
            }
        }

        // x-contribution: acc = acc + bias + att * P2[src]  (batched 2 rows)
#pragma unroll
        for (int b = 0; b < 4; b++) {
            ull pvp[2][8];
#pragma unroll
            for (int i2 = 0; i2 < 2; i2++) {
                int s = ssrc[wrp * 8 + b * 2 + i2];
                const float* pp = g_P2 + (size_t)s * 512;
#pragma unroll
                for (int jj = 0; jj < 8; jj++) {
                    float2 v2 = *(const float2*)(pp + co[jj]);
                    pvp[i2][jj] = pack2(v2.x, v2.y);
                }
            }
#pragma unroll
            for (int i2 = 0; i2 < 2; i2++) {
                int i = b * 2 + i2;
                float a = satt[wrp * 8 + i];
                ull ap = pack2(a, a);
#pragma unroll
                for (int jj = 0; jj < 8; jj++)
                    accp[i][jj] = ffma2_(ap, pvp[i2][jj], add2_(accp[i][jj], bcp[jj]));
            }
        }

        // gate activations + c/h update (h written in place; all u reads done)
#pragma unroll
        for (int i = 0; i < 8; i++) {
#pragma unroll
            for (int cs = 0; cs < 2; cs++) {
                float2 iv = unpack2(accp[i][cs * 4 + 0]);
                float2 fv = unpack2(accp[i][cs * 4 + 1]);
                float2 gv = unpack2(accp[i][cs * 4 + 2]);
                float2 ov = unpack2(accp[i][cs * 4 + 3]);
                float2 cp2 = creg2[i][cs];
                float c0 = fmaf(sig_fast(fv.x), cp2.x, sig_fast(iv.x) * tanh_fast(gv.x));
                float c1 = fmaf(sig_fast(fv.y), cp2.y, sig_fast(iv.y) * tanh_fast(gv.y));
                creg2[i][cs] = make_float2(c0, c1);
                float2 hh = make_float2(sig_fast(ov.x) * tanh_fast(c0),
                                        sig_fast(ov.y) * tanh_fast(c1));
                *(float2*)(u + (wrp * 8 + i) * U_STR + (hl + 2 * cs) * 32 + 2 * p) = hh;
            }
        }
        __syncthreads();
    }

    // epilogue: final h in u
    for (int idx = tid; idx < 64 * 128; idx += 256) {
        int r = idx >> 7, d = idx & 127;
        int n = n0 + r;
        if (n < NN) {
            float v = u[r * U_STR + d] + out[(size_t)n * 128 + d] + bias[d];
            out[(size_t)n * 128 + d] = (v >= 0.0f) ? v : 0.01f * v;
        }
    }
}

// ---------------- launch ----------------
extern "C" void kernel_launch(void* const* d_in, const int* in_sizes, int n_in,
                              void* d_out, int out_size) {
    const float* x    = (const float*)d_in[0];
    const float* Wp   = (const float*)d_in[1];
    const float* asrc = (const float*)d_in[2];
    const float* atrg = (const float*)d_in[3];
    const float* Wsk  = (const float*)d_in[4];
    const float* bias = (const float*)d_in[5];
    // d_in[6..9]: forward-direction weights, unused by the reference
    const float* wihb = (const float*)d_in[10];
    const float* whhb = (const float*)d_in[11];
    const float* bihb = (const float*)d_in[12];
    const float* bhhb = (const float*)d_in[13];
    const int*   ei   = (const int*)d_in[14];
    float* out = (float*)d_out;

    (void)in_sizes; (void)n_in; (void)out_size;

    cudaFuncSetAttribute(lstm_k, cudaFuncAttributeMaxDynamicSharedMemorySize,
                         LSTM_SM_FLOATS * (int)sizeof(float));

    prep_w_k<<<256, 256>>>(wihb, whhb, bihb, bhhb);
    gemm1_k<<<(NN + 63) / 64, 256>>>(x, Wp, Wsk, out);
    {
        dim3 g((NN + 63) / 64, 2);
        p2_k<<<g, 256>>>();
    }
    sdots_k<<<(NN * 32 + 255) / 256, 256>>>(asrc, atrg);
    initmax_k<<<1, 1>>>();
    scores_k<<<EE / 256, 256>>>(ei);
    sort_k<<<(NN + 255) / 256, 256>>>(ei);
    lstm_k<<<(NN + 63) / 64, 256, LSTM_SM_FLOATS * (int)sizeof(float)>>>(bias, out);
}